// round 8
// baseline (speedup 1.0000x reference)
#include <cuda_runtime.h>
#include <math.h>

#define Nn   15000
#define Ee   240000
#define ETOT (Ee + Nn)
#define DIN  2000
#define HID  128
#define EMBD 64
#define NCLS 33
#define NL   3
#define NH   4
#define NHH  (NH * HID)   // 512
#define NEGS 0.2f
#define EPSF 1e-5f

// ---------------- scratch (static device memory; no allocs allowed) ----------
__device__ float g_h   [Nn * HID];
__device__ float g_t   [Nn * HID];
__device__ float g_xl  [Nn * NHH];
__device__ float g_xr  [Nn * NHH];
__device__ float g_ea  [ETOT * 4];
__device__ float g_sc  [ETOT * NH];   // CSR-ordered raw scores
__device__ float g_al  [ETOT * NH];   // CSR-ordered normalized alphas
__device__ float g_out [Nn * HID];
__device__ float g_red [4];
__device__ float g_col [2 * HID];
__device__ float g_h1  [Nn * HID];
__device__ float g_e2  [Nn * EMBD];
__device__ float g_emb [Nn * EMBD];
__device__ float g_c1  [Nn * EMBD];
__device__ int g_deg   [Nn];
__device__ int g_rowptr[Nn + 1];
__device__ int g_cur   [Nn];
__device__ int g_eid   [ETOT];
__device__ int g_esrc  [ETOT];

// ---------------- helpers ----------------------------------------------------
__device__ __forceinline__ float geluf(float x) {
    return 0.5f * x * (1.0f + erff(x * 0.70710678118654752f));
}

__device__ __forceinline__ unsigned f2tf(float f) {
    unsigned r;
    asm("cvt.rna.tf32.f32 %0, %1;" : "=r"(r) : "f"(f));
    return r;
}

__global__ void k_fill(float* p, float v, int n) {
    int i = blockIdx.x * blockDim.x + threadIdx.x;
    if (i < n) p[i] = v;
}

__global__ void k_zeroi(int* p, int n) {
    int i = blockIdx.x * blockDim.x + threadIdx.x;
    if (i < n) p[i] = 0;
}

// ---------------- CSR build --------------------------------------------------
__global__ void k_hist(const int* __restrict__ ei) {
    int e = blockIdx.x * blockDim.x + threadIdx.x;
    if (e >= ETOT) return;
    int dst = (e < Ee) ? ei[Ee + e] : e - Ee;
    atomicAdd(&g_deg[dst], 1);
}

__global__ void k_scan() {
    __shared__ int sh[1024];
    const int C = 15;
    int t = threadIdx.x;
    int base = t * C;
    int local[C];
    int s = 0;
    for (int i = 0; i < C; i++) {
        int idx = base + i;
        int v = (idx < Nn) ? g_deg[idx] : 0;
        local[i] = s;
        s += v;
    }
    sh[t] = s;
    __syncthreads();
    for (int o = 1; o < 1024; o <<= 1) {
        int v = (t >= o) ? sh[t - o] : 0;
        __syncthreads();
        sh[t] += v;
        __syncthreads();
    }
    int off = (t > 0) ? sh[t - 1] : 0;
    for (int i = 0; i < C; i++) {
        int idx = base + i;
        if (idx < Nn) {
            g_rowptr[idx] = off + local[i];
            g_cur[idx]    = off + local[i];
        }
    }
    if (t == 1023) g_rowptr[Nn] = sh[1023];
}

__global__ void k_scatter(const int* __restrict__ ei) {
    int e = blockIdx.x * blockDim.x + threadIdx.x;
    if (e >= ETOT) return;
    int src, dst;
    if (e < Ee) { src = ei[e]; dst = ei[Ee + e]; } else { src = dst = e - Ee; }
    int p = atomicAdd(&g_cur[dst], 1);
    g_eid[p]  = e;
    g_esrc[p] = src;
}

// ---------------- tf32 tensor-core GEMM --------------------------------------
template<int BN>
__global__ void __launch_bounds__(256)
tgemm(const float* __restrict__ A, const float* __restrict__ B,
      const float* __restrict__ bias, float* __restrict__ C,
      int M, int Nc, int K, int act) {
    constexpr int BM = 128, BK = 16;
    constexpr int WN = BN / 2;
    constexpr int NT = WN / 8;
    constexpr int NBF = (BK * BN / 4) / 256;
    __shared__ unsigned As[2][BK][BM + 4];
    __shared__ unsigned Bs[2][BK][BN + 4];

    const int tid  = threadIdx.x;
    const int lane = tid & 31;
    const int wid  = tid >> 5;
    const int m0   = (wid & 3) * 32;
    const int n0   = (wid >> 2) * WN;
    const int gp   = lane >> 2;
    const int tk   = lane & 3;
    const int bx   = blockIdx.x * BN;
    const int by   = blockIdx.y * BM;

    float4 pa[2], pb[NBF];
    float acc[2][NT][4];
#pragma unroll
    for (int i = 0; i < 2; i++)
#pragma unroll
        for (int j = 0; j < NT; j++)
#pragma unroll
            for (int q = 0; q < 4; q++) acc[i][j][q] = 0.0f;

    const int nt = K / BK;

    auto loadA = [&](int k0) {
#pragma unroll
        for (int i = 0; i < 2; i++) {
            int f = tid + 256 * i;
            int row = by + (f >> 2);
            int kc  = k0 + (f & 3) * 4;
            pa[i] = (row < M) ? *(const float4*)(A + (long)row * K + kc)
                              : make_float4(0.f, 0.f, 0.f, 0.f);
        }
    };
    auto loadB = [&](int k0) {
#pragma unroll
        for (int i = 0; i < NBF; i++) {
            int f  = tid + 256 * i;
            int kr = k0 + f / (BN / 4);
            int c  = bx + (f % (BN / 4)) * 4;
            if (c + 3 < Nc) {
                pb[i] = *(const float4*)(B + (long)kr * Nc + c);
            } else {
                float4 v;
                v.x = (c     < Nc) ? B[(long)kr * Nc + c    ] : 0.f;
                v.y = (c + 1 < Nc) ? B[(long)kr * Nc + c + 1] : 0.f;
                v.z = (c + 2 < Nc) ? B[(long)kr * Nc + c + 2] : 0.f;
                v.w = (c + 3 < Nc) ? B[(long)kr * Nc + c + 3] : 0.f;
                pb[i] = v;
            }
        }
    };
    auto store = [&](int d) {
#pragma unroll
        for (int i = 0; i < 2; i++) {
            int f = tid + 256 * i;
            int row = f >> 2; int kq = (f & 3) * 4;
            As[d][kq + 0][row] = f2tf(pa[i].x);
            As[d][kq + 1][row] = f2tf(pa[i].y);
            As[d][kq + 2][row] = f2tf(pa[i].z);
            As[d][kq + 3][row] = f2tf(pa[i].w);
        }
#pragma unroll
        for (int i = 0; i < NBF; i++) {
            int f  = tid + 256 * i;
            int kr = f / (BN / 4);
            int c4 = (f % (BN / 4)) * 4;
            Bs[d][kr][c4 + 0] = f2tf(pb[i].x);
            Bs[d][kr][c4 + 1] = f2tf(pb[i].y);
            Bs[d][kr][c4 + 2] = f2tf(pb[i].z);
            Bs[d][kr][c4 + 3] = f2tf(pb[i].w);
        }
    };

    loadA(0); loadB(0); store(0);
    __syncthreads();

    for (int t = 0; t < nt; t++) {
        const int s = t & 1;
        if (t + 1 < nt) { loadA((t + 1) * BK); loadB((t + 1) * BK); }
#pragma unroll
        for (int k8 = 0; k8 < BK; k8 += 8) {
            unsigned a[2][4], b[NT][2];
#pragma unroll
            for (int mt = 0; mt < 2; mt++) {
                int mr = m0 + mt * 16;
                a[mt][0] = As[s][k8 + tk    ][mr + gp    ];
                a[mt][1] = As[s][k8 + tk    ][mr + gp + 8];
                a[mt][2] = As[s][k8 + tk + 4][mr + gp    ];
                a[mt][3] = As[s][k8 + tk + 4][mr + gp + 8];
            }
#pragma unroll
            for (int j = 0; j < NT; j++) {
                int nc = n0 + j * 8 + gp;
                b[j][0] = Bs[s][k8 + tk    ][nc];
                b[j][1] = Bs[s][k8 + tk + 4][nc];
            }
#pragma unroll
            for (int mt = 0; mt < 2; mt++)
#pragma unroll
                for (int j = 0; j < NT; j++) {
                    asm volatile(
                        "mma.sync.aligned.m16n8k8.row.col.f32.tf32.tf32.f32 "
                        "{%0,%1,%2,%3}, {%4,%5,%6,%7}, {%8,%9}, {%0,%1,%2,%3};\n"
                        : "+f"(acc[mt][j][0]), "+f"(acc[mt][j][1]),
                          "+f"(acc[mt][j][2]), "+f"(acc[mt][j][3])
                        : "r"(a[mt][0]), "r"(a[mt][1]), "r"(a[mt][2]), "r"(a[mt][3]),
                          "r"(b[j][0]), "r"(b[j][1]));
                }
        }
        if (t + 1 < nt) {
            store(s ^ 1);
            __syncthreads();
        }
    }

#pragma unroll
    for (int mt = 0; mt < 2; mt++) {
        int r0 = by + m0 + mt * 16 + gp;
        int r1 = r0 + 8;
#pragma unroll
        for (int j = 0; j < NT; j++) {
            int c0 = bx + n0 + j * 8 + tk * 2;
            if (r0 < M) {
                if (c0 < Nc) {
                    float v = acc[mt][j][0] + bias[c0];
                    C[(long)r0 * Nc + c0] = act ? geluf(v) : v;
                }
                if (c0 + 1 < Nc) {
                    float v = acc[mt][j][1] + bias[c0 + 1];
                    C[(long)r0 * Nc + c0 + 1] = act ? geluf(v) : v;
                }
            }
            if (r1 < M) {
                if (c0 < Nc) {
                    float v = acc[mt][j][2] + bias[c0];
                    C[(long)r1 * Nc + c0] = act ? geluf(v) : v;
                }
                if (c0 + 1 < Nc) {
                    float v = acc[mt][j][3] + bias[c0 + 1];
                    C[(long)r1 * Nc + c0 + 1] = act ? geluf(v) : v;
                }
            }
        }
    }
}

// ---------------- small SIMT GEMM (for Nc=33 classifier) ---------------------
template<int BN, int TN>
__global__ void __launch_bounds__(256)
sgemm_db(const float* __restrict__ A, const float* __restrict__ B,
         const float* __restrict__ bias, float* __restrict__ C,
         int M, int Nc, int K, int act) {
    constexpr int BM = 128, BK = 16, TM = 8;
    constexpr int NBF = (BK * BN / 4) / 256;
    __shared__ float As[2][BK][BM + 4];
    __shared__ float Bs[2][BK][BN + 4];
    const int tid = threadIdx.x;
    const int tx  = tid % (BN / TN);
    const int ty  = tid / (BN / TN);
    const int bx  = blockIdx.x * BN;
    const int by  = blockIdx.y * BM;
    const bool bvec = ((Nc & 3) == 0);

    float4 pa[2], pb[NBF];
    float acc[TM][TN];
#pragma unroll
    for (int i = 0; i < TM; i++)
#pragma unroll
        for (int j = 0; j < TN; j++) acc[i][j] = 0.0f;

    const int nt = K / BK;

#pragma unroll
    for (int i = 0; i < 2; i++) {
        int f = tid + 256 * i;
        int row = by + (f >> 2);
        int kc  = (f & 3) * 4;
        pa[i] = (row < M) ? *(const float4*)(A + (long)row * K + kc)
                          : make_float4(0.f, 0.f, 0.f, 0.f);
    }
#pragma unroll
    for (int i = 0; i < NBF; i++) {
        int f  = tid + 256 * i;
        int kr = f / (BN / 4);
        int c  = bx + (f % (BN / 4)) * 4;
        if (bvec && c + 3 < Nc) {
            pb[i] = *(const float4*)(B + (long)kr * Nc + c);
        } else {
            float4 v;
            v.x = (c     < Nc) ? B[(long)kr * Nc + c    ] : 0.f;
            v.y = (c + 1 < Nc) ? B[(long)kr * Nc + c + 1] : 0.f;
            v.z = (c + 2 < Nc) ? B[(long)kr * Nc + c + 2] : 0.f;
            v.w = (c + 3 < Nc) ? B[(long)kr * Nc + c + 3] : 0.f;
            pb[i] = v;
        }
    }
#pragma unroll
    for (int i = 0; i < 2; i++) {
        int f = tid + 256 * i;
        int row = f >> 2; int kq = (f & 3) * 4;
        As[0][kq + 0][row] = pa[i].x;
        As[0][kq + 1][row] = pa[i].y;
        As[0][kq + 2][row] = pa[i].z;
        As[0][kq + 3][row] = pa[i].w;
    }
#pragma unroll
    for (int i = 0; i < NBF; i++) {
        int f  = tid + 256 * i;
        int kr = f / (BN / 4);
        int c4 = (f % (BN / 4)) * 4;
        *(float4*)&Bs[0][kr][c4] = pb[i];
    }
    __syncthreads();

    for (int t = 0; t < nt; t++) {
        const int s = t & 1;
        if (t + 1 < nt) {
            const int k0 = (t + 1) * BK;
#pragma unroll
            for (int i = 0; i < 2; i++) {
                int f = tid + 256 * i;
                int row = by + (f >> 2);
                int kc  = k0 + (f & 3) * 4;
                pa[i] = (row < M) ? *(const float4*)(A + (long)row * K + kc)
                                  : make_float4(0.f, 0.f, 0.f, 0.f);
            }
#pragma unroll
            for (int i = 0; i < NBF; i++) {
                int f  = tid + 256 * i;
                int kr = k0 + f / (BN / 4);
                int c  = bx + (f % (BN / 4)) * 4;
                if (bvec && c + 3 < Nc) {
                    pb[i] = *(const float4*)(B + (long)kr * Nc + c);
                } else {
                    float4 v;
                    v.x = (c     < Nc) ? B[(long)kr * Nc + c    ] : 0.f;
                    v.y = (c + 1 < Nc) ? B[(long)kr * Nc + c + 1] : 0.f;
                    v.z = (c + 2 < Nc) ? B[(long)kr * Nc + c + 2] : 0.f;
                    v.w = (c + 3 < Nc) ? B[(long)kr * Nc + c + 3] : 0.f;
                    pb[i] = v;
                }
            }
        }
#pragma unroll
        for (int kk = 0; kk < BK; kk++) {
            float a[TM], b[TN];
            *(float4*)&a[0] = *(const float4*)&As[s][kk][ty * TM + 0];
            *(float4*)&a[4] = *(const float4*)&As[s][kk][ty * TM + 4];
#pragma unroll
            for (int j = 0; j < TN; j += 4)
                *(float4*)&b[j] = *(const float4*)&Bs[s][kk][tx * TN + j];
#pragma unroll
            for (int i = 0; i < TM; i++)
#pragma unroll
                for (int j = 0; j < TN; j++)
                    acc[i][j] = fmaf(a[i], b[j], acc[i][j]);
        }
        if (t + 1 < nt) {
            const int d = s ^ 1;
#pragma unroll
            for (int i = 0; i < 2; i++) {
                int f = tid + 256 * i;
                int row = f >> 2; int kq = (f & 3) * 4;
                As[d][kq + 0][row] = pa[i].x;
                As[d][kq + 1][row] = pa[i].y;
                As[d][kq + 2][row] = pa[i].z;
                As[d][kq + 3][row] = pa[i].w;
            }
#pragma unroll
            for (int i = 0; i < NBF; i++) {
                int f  = tid + 256 * i;
                int kr = f / (BN / 4);
                int c4 = (f % (BN / 4)) * 4;
                *(float4*)&Bs[d][kr][c4] = pb[i];
            }
            __syncthreads();
        }
    }

#pragma unroll
    for (int i = 0; i < TM; i++) {
        int r = by + ty * TM + i;
        if (r >= M) continue;
#pragma unroll
        for (int j = 0; j < TN; j++) {
            int c = bx + tx * TN + j;
            if (c < Nc) {
                float v = acc[i][j] + bias[c];
                C[(long)r * Nc + c] = act ? geluf(v) : v;
            }
        }
    }
}

// ---------------- LayerNorm (+optional GELU), warp per row -------------------
__global__ void ln_act(const float* __restrict__ X, const float* __restrict__ g,
                       const float* __restrict__ b, float* __restrict__ Y,
                       int M, int D, int act) {
    int warp = (blockIdx.x * blockDim.x + threadIdx.x) >> 5;
    int lane = threadIdx.x & 31;
    if (warp >= M) return;
    const float* x = X + (long)warp * D;
    int nv = D >> 5;
    float v[4];
    float s = 0.0f;
    for (int i = 0; i < nv; i++) { v[i] = x[lane + 32 * i]; s += v[i]; }
#pragma unroll
    for (int o = 16; o; o >>= 1) s += __shfl_xor_sync(0xFFFFFFFFu, s, o);
    float mean = s / (float)D;
    float q = 0.0f;
    for (int i = 0; i < nv; i++) { float d = v[i] - mean; q += d * d; }
#pragma unroll
    for (int o = 16; o; o >>= 1) q += __shfl_xor_sync(0xFFFFFFFFu, q, o);
    float inv = rsqrtf(q / (float)D + EPSF);
    float* y = Y + (long)warp * D;
    for (int i = 0; i < nv; i++) {
        int c = lane + 32 * i;
        float o2 = (v[i] - mean) * inv * g[c] + b[c];
        y[c] = act ? geluf(o2) : o2;
    }
}

// ---------------- edge feature construction ----------------------------------
__global__ void k_edge1(const float* __restrict__ pos, const int* __restrict__ ei) {
    int e = blockIdx.x * blockDim.x + threadIdx.x;
    float sd = 0.f, sx = 0.f, sy = 0.f, si = 0.f;
    if (e < Ee) {
        int r = ei[e], c = ei[Ee + e];
        float dx = pos[2 * c] - pos[2 * r];
        float dy = pos[2 * c + 1] - pos[2 * r + 1];
        float dist = sqrtf(dx * dx + dy * dy);
        dist = fmaxf(dist, 1e-6f);
        float ix = dx / dist, iy = dy / dist;
        g_ea[e * 4 + 0] = ix;
        g_ea[e * 4 + 1] = iy;
        g_ea[e * 4 + 2] = dist;
        sd = dist; sx = ix; sy = iy; si = 1.0f / dist;
    }
#pragma unroll
    for (int o = 16; o; o >>= 1) {
        sd += __shfl_xor_sync(0xFFFFFFFFu, sd, o);
        sx += __shfl_xor_sync(0xFFFFFFFFu, sx, o);
        sy += __shfl_xor_sync(0xFFFFFFFFu, sy, o);
        si += __shfl_xor_sync(0xFFFFFFFFu, si, o);
    }
    if ((threadIdx.x & 31) == 0) {
        atomicAdd(&g_red[0], sd);
        atomicAdd(&g_red[1], sx);
        atomicAdd(&g_red[2], sy);
        atomicAdd(&g_red[3], si);
    }
}

__global__ void k_edge2() {
    int i = blockIdx.x * blockDim.x + threadIdx.x;
    if (i >= ETOT) return;
    float md = fmaxf(g_red[0] / (float)Ee, 1e-6f);
    if (i < Ee) {
        float d = g_ea[i * 4 + 2];
        g_ea[i * 4 + 2] = d / md;
        g_ea[i * 4 + 3] = md / d;
    } else {
        g_ea[i * 4 + 0] = g_red[1] / (float)Ee;
        g_ea[i * 4 + 1] = g_red[2] / (float)Ee;
        g_ea[i * 4 + 2] = g_red[0] / ((float)Ee * md);
        g_ea[i * 4 + 3] = md * g_red[3] / (float)Ee;
    }
}

// ---------------- fused GATv2 score + softmax (warp per dst node) ------------
// Each warp owns one dst node: xr[dst] loaded once into registers, then the
// incident-edge list (CSR) is streamed: score -> running max; then exp+sum;
// then scale. Scores/alphas stored in CSR order.
__global__ void k_attn(const float* __restrict__ We, const float* __restrict__ att) {
    __shared__ float sWe[4 * NHH];
    __shared__ float sAtt[NHH];
    for (int i = threadIdx.x; i < 4 * NHH; i += blockDim.x) sWe[i] = We[i];
    for (int i = threadIdx.x; i < NHH; i += blockDim.x) sAtt[i] = att[i];
    __syncthreads();

    int w = blockIdx.x * 8 + (threadIdx.x >> 5);
    if (w >= Nn) return;
    int lane = threadIdx.x & 31;
    int s0 = g_rowptr[w], s1 = g_rowptr[w + 1];

    // xr[dst] resident in registers: value i is column lane + 32*i
    float xr[16];
    const float* pr = g_xr + (long)w * NHH;
#pragma unroll
    for (int i = 0; i < 16; i++) xr[i] = pr[lane + 32 * i];

    float mx0 = -1e30f, mx1 = -1e30f, mx2 = -1e30f, mx3 = -1e30f;

    // pass 1: scores + running max
    for (int k = s0; k < s1; k++) {
        int src = g_esrc[k];
        float4 ea = *(const float4*)&g_ea[g_eid[k] * 4];
        const float* pl = g_xl + (long)src * NHH;
        float p0 = 0.f, p1 = 0.f, p2 = 0.f, p3 = 0.f;
#pragma unroll
        for (int i = 0; i < 16; i++) {
            int c = lane + 32 * i;
            float v = pl[c] + xr[i]
                    + ea.x * sWe[c] + ea.y * sWe[NHH + c]
                    + ea.z * sWe[2 * NHH + c] + ea.w * sWe[3 * NHH + c];
            v = v > 0.0f ? v : NEGS * v;
            float pv = v * sAtt[c];
            if (i < 4)       p0 += pv;
            else if (i < 8)  p1 += pv;
            else if (i < 12) p2 += pv;
            else             p3 += pv;
        }
#pragma unroll
        for (int o = 16; o; o >>= 1) {
            p0 += __shfl_xor_sync(0xFFFFFFFFu, p0, o);
            p1 += __shfl_xor_sync(0xFFFFFFFFu, p1, o);
            p2 += __shfl_xor_sync(0xFFFFFFFFu, p2, o);
            p3 += __shfl_xor_sync(0xFFFFFFFFu, p3, o);
        }
        mx0 = fmaxf(mx0, p0); mx1 = fmaxf(mx1, p1);
        mx2 = fmaxf(mx2, p2); mx3 = fmaxf(mx3, p3);
        if (lane == 0) *(float4*)&g_sc[k * NH] = make_float4(p0, p1, p2, p3);
    }

    // pass 2: exp + sums (scores are L1/L2-hot, 16B per edge)
    float u0 = 0.f, u1 = 0.f, u2 = 0.f, u3 = 0.f;
    for (int k = s0; k < s1; k++) {
        float4 sc = *(const float4*)&g_sc[k * NH];
        float e0 = expf(sc.x - mx0), e1 = expf(sc.y - mx1);
        float e2 = expf(sc.z - mx2), e3 = expf(sc.w - mx3);
        u0 += e0; u1 += e1; u2 += e2; u3 += e3;
        if (lane == 0) *(float4*)&g_al[k * NH] = make_float4(e0, e1, e2, e3);
    }
    float i0 = 1.0f / u0, i1 = 1.0f / u1, i2 = 1.0f / u2, i3 = 1.0f / u3;

    // pass 3: normalize
    if (lane == 0) {
        for (int k = s0; k < s1; k++) {
            float4 a = *(const float4*)&g_al[k * NH];
            a.x *= i0; a.y *= i1; a.z *= i2; a.w *= i3;
            *(float4*)&g_al[k * NH] = a;
        }
    }
}

// ---------------- aggregation (warp per dst node, atomic-free) ---------------
__global__ void k_agg2() {
    int w = (blockIdx.x * blockDim.x + threadIdx.x) >> 5;
    if (w >= Nn) return;
    int lane = threadIdx.x & 31;
    int s0 = g_rowptr[w], s1 = g_rowptr[w + 1];
    float a0 = 0.f, a1 = 0.f, a2 = 0.f, a3 = 0.f;
    const int c0 = lane, c1 = lane + 32, c2 = lane + 64, c3 = lane + 96;
    for (int k = s0; k < s1; k++) {
        float4 al = *(const float4*)&g_al[k * NH];
        const float* pl = g_xl + (long)g_esrc[k] * NHH;
        a0 += al.x * pl[c0] + al.y * pl[HID + c0] + al.z * pl[2 * HID + c0] + al.w * pl[3 * HID + c0];
        a1 += al.x * pl[c1] + al.y * pl[HID + c1] + al.z * pl[2 * HID + c1] + al.w * pl[3 * HID + c1];
        a2 += al.x * pl[c2] + al.y * pl[HID + c2] + al.z * pl[2 * HID + c2] + al.w * pl[3 * HID + c2];
        a3 += al.x * pl[c3] + al.y * pl[HID + c3] + al.z * pl[2 * HID + c3] + al.w * pl[3 * HID + c3];
    }
    float* o = g_out + (long)w * HID;
    o[c0] = 0.25f * a0;
    o[c1] = 0.25f * a1;
    o[c2] = 0.25f * a2;
    o[c3] = 0.25f * a3;
}

// ---------------- GraphNorm (3 passes over [N,128]) --------------------------
__global__ void k_colsum_bias(const float* __restrict__ bias, int M) {
    int col = threadIdx.x & 127;
    int half = threadIdx.x >> 7;
    int r0 = blockIdx.x * 128;
    int rend = min(r0 + 128, M);
    float s = 0.0f;
    for (int r = r0 + half; r < rend; r += 2) {
        float v = g_out[r * HID + col] + bias[col];
        g_out[r * HID + col] = v;
        s += v;
    }
    __shared__ float sh[256];
    sh[threadIdx.x] = s;
    __syncthreads();
    if (half == 0) atomicAdd(&g_col[col], sh[col] + sh[128 + col]);
}

__global__ void k_center_ss(const float* __restrict__ ga, int M) {
    int col = threadIdx.x & 127;
    int half = threadIdx.x >> 7;
    int r0 = blockIdx.x * 128;
    int rend = min(r0 + 128, M);
    float mu = g_col[col] / (float)M;
    float s = 0.0f;
    for (int r = r0 + half; r < rend; r += 2) {
        float v = g_out[r * HID + col] - ga[col] * mu;
        g_out[r * HID + col] = v;
        s += v * v;
    }
    __shared__ float sh[256];
    sh[threadIdx.x] = s;
    __syncthreads();
    if (half == 0) atomicAdd(&g_col[128 + col], sh[col] + sh[128 + col]);
}

__global__ void k_finish(const float* __restrict__ w, const float* __restrict__ b, int M) {
    int i = blockIdx.x * blockDim.x + threadIdx.x;
    if (i >= M * HID) return;
    int col = i & 127;
    float inv = rsqrtf(g_col[128 + col] / (float)M + EPSF);
    float y = g_out[i] * inv * w[col] + b[col];
    g_h[i] = geluf(y) + g_h[i];
}

// ---------------- host orchestration -----------------------------------------
extern "C" void kernel_launch(void* const* d_in, const int* in_sizes, int n_in,
                              void* d_out, int out_size) {
    const float* x        = (const float*)d_in[0];
    const int*   ei       = (const int*)  d_in[1];
    const float* pos      = (const float*)d_in[2];
    const float* in_W     = (const float*)d_in[3];
    const float* in_b     = (const float*)d_in[4];
    const float* in_ln_g  = (const float*)d_in[5];
    const float* in_ln_b  = (const float*)d_in[6];
    const float* conv_Wl  = (const float*)d_in[7];
    const float* conv_bl  = (const float*)d_in[8];
    const float* conv_Wr  = (const float*)d_in[9];
    const float* conv_br  = (const float*)d_in[10];
    const float* conv_We  = (const float*)d_in[11];
    const float* conv_att = (const float*)d_in[12];
    const float* conv_b   = (const float*)d_in[13];
    const float* gn_w     = (const float*)d_in[14];
    const float* gn_b     = (const float*)d_in[15];
    const float* gn_a     = (const float*)d_in[16];
    const float* emb_W1   = (const float*)d_in[17];
    const float* emb_b1   = (const float*)d_in[18];
    const float* emb_ln1g = (const float*)d_in[19];
    const float* emb_ln1b = (const float*)d_in[20];
    const float* emb_W2   = (const float*)d_in[21];
    const float* emb_b2   = (const float*)d_in[22];
    const float* emb_ln2g = (const float*)d_in[23];
    const float* emb_ln2b = (const float*)d_in[24];
    const float* cls_W1   = (const float*)d_in[25];
    const float* cls_b1   = (const float*)d_in[26];
    const float* cls_W2   = (const float*)d_in[27];
    const float* cls_b2   = (const float*)d_in[28];

    float *p_h, *p_t, *p_xl, *p_xr, *p_red, *p_col, *p_h1, *p_e2, *p_emb, *p_c1;
    int *p_deg;
    cudaGetSymbolAddress((void**)&p_h,    g_h);
    cudaGetSymbolAddress((void**)&p_t,    g_t);
    cudaGetSymbolAddress((void**)&p_xl,   g_xl);
    cudaGetSymbolAddress((void**)&p_xr,   g_xr);
    cudaGetSymbolAddress((void**)&p_red,  g_red);
    cudaGetSymbolAddress((void**)&p_col,  g_col);
    cudaGetSymbolAddress((void**)&p_h1,   g_h1);
    cudaGetSymbolAddress((void**)&p_e2,   g_e2);
    cudaGetSymbolAddress((void**)&p_emb,  g_emb);
    cudaGetSymbolAddress((void**)&p_c1,   g_c1);
    cudaGetSymbolAddress((void**)&p_deg,  g_deg);

    const int T = 256;
    const int GY = (Nn + 127) / 128;   // 118
    const int NWARP_GRID = (Nn * 32 + T - 1) / T;

    // ---- CSR build ----
    k_zeroi<<<(Nn + T - 1) / T, T>>>(p_deg, Nn);
    k_hist<<<(ETOT + T - 1) / T, T>>>(ei);
    k_scan<<<1, 1024>>>();
    k_scatter<<<(ETOT + T - 1) / T, T>>>(ei);

    // ---- edge features ----
    k_fill<<<1, 32>>>(p_red, 0.0f, 4);
    k_edge1<<<(Ee + T - 1) / T, T>>>(pos, ei);
    k_edge2<<<(ETOT + T - 1) / T, T>>>();

    // ---- input projection (tf32 tensor cores) ----
    tgemm<64><<<dim3(2, GY), 256>>>(x, in_W, in_b, p_t, Nn, HID, DIN, 0);
    ln_act<<<NWARP_GRID, T>>>(p_t, in_ln_g, in_ln_b, p_h, Nn, HID, 1);

    // ---- GAT layers ----
    for (int l = 0; l < NL; l++) {
        const float* Wl = conv_Wl + (long)l * HID * NHH;
        const float* bl = conv_bl + (long)l * NHH;
        const float* Wr = conv_Wr + (long)l * HID * NHH;
        const float* br = conv_br + (long)l * NHH;
        const float* We = conv_We + (long)l * 4 * NHH;
        const float* at = conv_att + (long)l * NHH;
        const float* cb = conv_b + (long)l * HID;
        const float* ga = gn_a + (long)l * HID;
        const float* gw = gn_w + (long)l * HID;
        const float* gb = gn_b + (long)l * HID;

        k_fill<<<1, 256>>>(p_col, 0.0f, 256);

        tgemm<128><<<dim3(4, GY), 256>>>(p_h, Wl, bl, p_xl, Nn, NHH, HID, 0);
        tgemm<128><<<dim3(4, GY), 256>>>(p_h, Wr, br, p_xr, Nn, NHH, HID, 0);

        k_attn<<<(Nn + 7) / 8, 256>>>(We, at);
        k_agg2<<<NWARP_GRID, T>>>();

        int nb = (Nn + 127) / 128;
        k_colsum_bias<<<nb, 256>>>(cb, Nn);
        k_center_ss<<<nb, 256>>>(ga, Nn);
        k_finish<<<(Nn * HID + T - 1) / T, T>>>(gw, gb, Nn);
    }

    // ---- embedding head ----
    tgemm<64><<<dim3(2, GY), 256>>>(p_h, emb_W1, emb_b1, p_t, Nn, HID, HID, 0);
    ln_act<<<NWARP_GRID, T>>>(p_t, emb_ln1g, emb_ln1b, p_h1, Nn, HID, 1);
    tgemm<64><<<dim3(1, GY), 256>>>(p_h1, emb_W2, emb_b2, p_e2, Nn, EMBD, HID, 0);
    ln_act<<<NWARP_GRID, T>>>(p_e2, emb_ln2g, emb_ln2b, p_emb, Nn, EMBD, 0);
    tgemm<64><<<dim3(1, GY), 256>>>(p_emb, cls_W1, cls_b1, p_c1, Nn, EMBD, EMBD, 1);
    sgemm_db<64, 4><<<dim3(1, GY), 256>>>(p_c1, cls_W2, cls_b2, (float*)d_out, Nn, NCLS, EMBD, 0);
}

// round 9
// speedup vs baseline: 1.0648x; 1.0648x over previous
#include <cuda_runtime.h>
#include <math.h>

#define Nn   15000
#define Ee   240000
#define ETOT (Ee + Nn)
#define DIN  2000
#define HID  128
#define EMBD 64
#define NCLS 33
#define NL   3
#define NH   4
#define NHH  (NH * HID)   // 512
#define NEGS 0.2f
#define EPSF 1e-5f

// ---------------- scratch (static device memory; no allocs allowed) ----------
__device__ float g_h   [Nn * HID];
__device__ float g_t   [Nn * HID];
__device__ float g_xl  [Nn * NHH];
__device__ float g_xr  [Nn * NHH];
__device__ float g_ea  [ETOT * 4];
__device__ float g_sc  [ETOT * NH];   // CSR-ordered raw scores
__device__ float g_out [Nn * HID];
__device__ float g_red [4];
__device__ float g_col [2 * HID];
__device__ float g_h1  [Nn * HID];
__device__ float g_e2  [Nn * EMBD];
__device__ float g_emb [Nn * EMBD];
__device__ float g_c1  [Nn * EMBD];
__device__ int g_deg   [Nn];
__device__ int g_rowptr[Nn + 1];
__device__ int g_cur   [Nn];
__device__ int g_eid   [ETOT];
__device__ int g_esrc  [ETOT];

// ---------------- helpers ----------------------------------------------------
__device__ __forceinline__ float geluf(float x) {
    return 0.5f * x * (1.0f + erff(x * 0.70710678118654752f));
}

__device__ __forceinline__ unsigned f2tf(float f) {
    unsigned r;
    asm("cvt.rna.tf32.f32 %0, %1;" : "=r"(r) : "f"(f));
    return r;
}

__global__ void k_fill(float* p, float v, int n) {
    int i = blockIdx.x * blockDim.x + threadIdx.x;
    if (i < n) p[i] = v;
}

__global__ void k_zeroi(int* p, int n) {
    int i = blockIdx.x * blockDim.x + threadIdx.x;
    if (i < n) p[i] = 0;
}

// ---------------- CSR build --------------------------------------------------
__global__ void k_hist(const int* __restrict__ ei) {
    int e = blockIdx.x * blockDim.x + threadIdx.x;
    if (e >= ETOT) return;
    int dst = (e < Ee) ? ei[Ee + e] : e - Ee;
    atomicAdd(&g_deg[dst], 1);
}

__global__ void k_scan() {
    __shared__ int sh[1024];
    const int C = 15;
    int t = threadIdx.x;
    int base = t * C;
    int local[C];
    int s = 0;
    for (int i = 0; i < C; i++) {
        int idx = base + i;
        int v = (idx < Nn) ? g_deg[idx] : 0;
        local[i] = s;
        s += v;
    }
    sh[t] = s;
    __syncthreads();
    for (int o = 1; o < 1024; o <<= 1) {
        int v = (t >= o) ? sh[t - o] : 0;
        __syncthreads();
        sh[t] += v;
        __syncthreads();
    }
    int off = (t > 0) ? sh[t - 1] : 0;
    for (int i = 0; i < C; i++) {
        int idx = base + i;
        if (idx < Nn) {
            g_rowptr[idx] = off + local[i];
            g_cur[idx]    = off + local[i];
        }
    }
    if (t == 1023) g_rowptr[Nn] = sh[1023];
}

__global__ void k_scatter(const int* __restrict__ ei) {
    int e = blockIdx.x * blockDim.x + threadIdx.x;
    if (e >= ETOT) return;
    int src, dst;
    if (e < Ee) { src = ei[e]; dst = ei[Ee + e]; } else { src = dst = e - Ee; }
    int p = atomicAdd(&g_cur[dst], 1);
    g_eid[p]  = e;
    g_esrc[p] = src;
}

// ---------------- tf32 tensor-core GEMM core ---------------------------------
template<int BN>
__device__ __forceinline__ void tgemm_body(
    const float* __restrict__ A, const float* __restrict__ B,
    const float* __restrict__ bias, float* __restrict__ C,
    int M, int Nc, int K, int act, int bxBlk, int byBlk) {
    constexpr int BM = 128, BK = 16;
    constexpr int WN = BN / 2;
    constexpr int NT = WN / 8;
    constexpr int NBF = (BK * BN / 4) / 256;
    __shared__ unsigned As[2][BK][BM + 4];
    __shared__ unsigned Bs[2][BK][BN + 4];

    const int tid  = threadIdx.x;
    const int lane = tid & 31;
    const int wid  = tid >> 5;
    const int m0   = (wid & 3) * 32;
    const int n0   = (wid >> 2) * WN;
    const int gp   = lane >> 2;
    const int tk   = lane & 3;
    const int bx   = bxBlk * BN;
    const int by   = byBlk * BM;

    float4 pa[2], pb[NBF];
    float acc[2][NT][4];
#pragma unroll
    for (int i = 0; i < 2; i++)
#pragma unroll
        for (int j = 0; j < NT; j++)
#pragma unroll
            for (int q = 0; q < 4; q++) acc[i][j][q] = 0.0f;

    const int nt = K / BK;

    auto loadA = [&](int k0) {
#pragma unroll
        for (int i = 0; i < 2; i++) {
            int f = tid + 256 * i;
            int row = by + (f >> 2);
            int kc  = k0 + (f & 3) * 4;
            pa[i] = (row < M) ? *(const float4*)(A + (long)row * K + kc)
                              : make_float4(0.f, 0.f, 0.f, 0.f);
        }
    };
    auto loadB = [&](int k0) {
#pragma unroll
        for (int i = 0; i < NBF; i++) {
            int f  = tid + 256 * i;
            int kr = k0 + f / (BN / 4);
            int c  = bx + (f % (BN / 4)) * 4;
            if (c + 3 < Nc) {
                pb[i] = *(const float4*)(B + (long)kr * Nc + c);
            } else {
                float4 v;
                v.x = (c     < Nc) ? B[(long)kr * Nc + c    ] : 0.f;
                v.y = (c + 1 < Nc) ? B[(long)kr * Nc + c + 1] : 0.f;
                v.z = (c + 2 < Nc) ? B[(long)kr * Nc + c + 2] : 0.f;
                v.w = (c + 3 < Nc) ? B[(long)kr * Nc + c + 3] : 0.f;
                pb[i] = v;
            }
        }
    };
    auto store = [&](int d) {
#pragma unroll
        for (int i = 0; i < 2; i++) {
            int f = tid + 256 * i;
            int row = f >> 2; int kq = (f & 3) * 4;
            As[d][kq + 0][row] = f2tf(pa[i].x);
            As[d][kq + 1][row] = f2tf(pa[i].y);
            As[d][kq + 2][row] = f2tf(pa[i].z);
            As[d][kq + 3][row] = f2tf(pa[i].w);
        }
#pragma unroll
        for (int i = 0; i < NBF; i++) {
            int f  = tid + 256 * i;
            int kr = f / (BN / 4);
            int c4 = (f % (BN / 4)) * 4;
            Bs[d][kr][c4 + 0] = f2tf(pb[i].x);
            Bs[d][kr][c4 + 1] = f2tf(pb[i].y);
            Bs[d][kr][c4 + 2] = f2tf(pb[i].z);
            Bs[d][kr][c4 + 3] = f2tf(pb[i].w);
        }
    };

    loadA(0); loadB(0); store(0);
    __syncthreads();

    for (int t = 0; t < nt; t++) {
        const int s = t & 1;
        if (t + 1 < nt) { loadA((t + 1) * BK); loadB((t + 1) * BK); }
#pragma unroll
        for (int k8 = 0; k8 < BK; k8 += 8) {
            unsigned a[2][4], b[NT][2];
#pragma unroll
            for (int mt = 0; mt < 2; mt++) {
                int mr = m0 + mt * 16;
                a[mt][0] = As[s][k8 + tk    ][mr + gp    ];
                a[mt][1] = As[s][k8 + tk    ][mr + gp + 8];
                a[mt][2] = As[s][k8 + tk + 4][mr + gp    ];
                a[mt][3] = As[s][k8 + tk + 4][mr + gp + 8];
            }
#pragma unroll
            for (int j = 0; j < NT; j++) {
                int nc = n0 + j * 8 + gp;
                b[j][0] = Bs[s][k8 + tk    ][nc];
                b[j][1] = Bs[s][k8 + tk + 4][nc];
            }
#pragma unroll
            for (int mt = 0; mt < 2; mt++)
#pragma unroll
                for (int j = 0; j < NT; j++) {
                    asm volatile(
                        "mma.sync.aligned.m16n8k8.row.col.f32.tf32.tf32.f32 "
                        "{%0,%1,%2,%3}, {%4,%5,%6,%7}, {%8,%9}, {%0,%1,%2,%3};\n"
                        : "+f"(acc[mt][j][0]), "+f"(acc[mt][j][1]),
                          "+f"(acc[mt][j][2]), "+f"(acc[mt][j][3])
                        : "r"(a[mt][0]), "r"(a[mt][1]), "r"(a[mt][2]), "r"(a[mt][3]),
                          "r"(b[j][0]), "r"(b[j][1]));
                }
        }
        if (t + 1 < nt) {
            store(s ^ 1);
            __syncthreads();
        }
    }

#pragma unroll
    for (int mt = 0; mt < 2; mt++) {
        int r0 = by + m0 + mt * 16 + gp;
        int r1 = r0 + 8;
#pragma unroll
        for (int j = 0; j < NT; j++) {
            int c0 = bx + n0 + j * 8 + tk * 2;
            if (r0 < M) {
                if (c0 < Nc) {
                    float v = acc[mt][j][0] + bias[c0];
                    C[(long)r0 * Nc + c0] = act ? geluf(v) : v;
                }
                if (c0 + 1 < Nc) {
                    float v = acc[mt][j][1] + bias[c0 + 1];
                    C[(long)r0 * Nc + c0 + 1] = act ? geluf(v) : v;
                }
            }
            if (r1 < M) {
                if (c0 < Nc) {
                    float v = acc[mt][j][2] + bias[c0];
                    C[(long)r1 * Nc + c0] = act ? geluf(v) : v;
                }
                if (c0 + 1 < Nc) {
                    float v = acc[mt][j][3] + bias[c0 + 1];
                    C[(long)r1 * Nc + c0 + 1] = act ? geluf(v) : v;
                }
            }
        }
    }
}

template<int BN>
__global__ void __launch_bounds__(256)
tgemm(const float* __restrict__ A, const float* __restrict__ B,
      const float* __restrict__ bias, float* __restrict__ C,
      int M, int Nc, int K, int act) {
    tgemm_body<BN>(A, B, bias, C, M, Nc, K, act, blockIdx.x, blockIdx.y);
}

// dual GEMM: z=0 -> (B1,bias1,C1), z=1 -> (B2,bias2,C2); one grid for both.
template<int BN>
__global__ void __launch_bounds__(256)
tgemm2(const float* __restrict__ A,
       const float* __restrict__ B1, const float* __restrict__ bias1, float* __restrict__ C1,
       const float* __restrict__ B2, const float* __restrict__ bias2, float* __restrict__ C2,
       int M, int Nc, int K) {
    if (blockIdx.z == 0)
        tgemm_body<BN>(A, B1, bias1, C1, M, Nc, K, 0, blockIdx.x, blockIdx.y);
    else
        tgemm_body<BN>(A, B2, bias2, C2, M, Nc, K, 0, blockIdx.x, blockIdx.y);
}

// ---------------- small SIMT GEMM (for Nc=33 classifier) ---------------------
template<int BN, int TN>
__global__ void __launch_bounds__(256)
sgemm_db(const float* __restrict__ A, const float* __restrict__ B,
         const float* __restrict__ bias, float* __restrict__ C,
         int M, int Nc, int K, int act) {
    constexpr int BM = 128, BK = 16, TM = 8;
    constexpr int NBF = (BK * BN / 4) / 256;
    __shared__ float As[2][BK][BM + 4];
    __shared__ float Bs[2][BK][BN + 4];
    const int tid = threadIdx.x;
    const int tx  = tid % (BN / TN);
    const int ty  = tid / (BN / TN);
    const int bx  = blockIdx.x * BN;
    const int by  = blockIdx.y * BM;
    const bool bvec = ((Nc & 3) == 0);

    float4 pa[2], pb[NBF];
    float acc[TM][TN];
#pragma unroll
    for (int i = 0; i < TM; i++)
#pragma unroll
        for (int j = 0; j < TN; j++) acc[i][j] = 0.0f;

    const int nt = K / BK;

#pragma unroll
    for (int i = 0; i < 2; i++) {
        int f = tid + 256 * i;
        int row = by + (f >> 2);
        int kc  = (f & 3) * 4;
        pa[i] = (row < M) ? *(const float4*)(A + (long)row * K + kc)
                          : make_float4(0.f, 0.f, 0.f, 0.f);
    }
#pragma unroll
    for (int i = 0; i < NBF; i++) {
        int f  = tid + 256 * i;
        int kr = f / (BN / 4);
        int c  = bx + (f % (BN / 4)) * 4;
        if (bvec && c + 3 < Nc) {
            pb[i] = *(const float4*)(B + (long)kr * Nc + c);
        } else {
            float4 v;
            v.x = (c     < Nc) ? B[(long)kr * Nc + c    ] : 0.f;
            v.y = (c + 1 < Nc) ? B[(long)kr * Nc + c + 1] : 0.f;
            v.z = (c + 2 < Nc) ? B[(long)kr * Nc + c + 2] : 0.f;
            v.w = (c + 3 < Nc) ? B[(long)kr * Nc + c + 3] : 0.f;
            pb[i] = v;
        }
    }
#pragma unroll
    for (int i = 0; i < 2; i++) {
        int f = tid + 256 * i;
        int row = f >> 2; int kq = (f & 3) * 4;
        As[0][kq + 0][row] = pa[i].x;
        As[0][kq + 1][row] = pa[i].y;
        As[0][kq + 2][row] = pa[i].z;
        As[0][kq + 3][row] = pa[i].w;
    }
#pragma unroll
    for (int i = 0; i < NBF; i++) {
        int f  = tid + 256 * i;
        int kr = f / (BN / 4);
        int c4 = (f % (BN / 4)) * 4;
        *(float4*)&Bs[0][kr][c4] = pb[i];
    }
    __syncthreads();

    for (int t = 0; t < nt; t++) {
        const int s = t & 1;
        if (t + 1 < nt) {
            const int k0 = (t + 1) * BK;
#pragma unroll
            for (int i = 0; i < 2; i++) {
                int f = tid + 256 * i;
                int row = by + (f >> 2);
                int kc  = k0 + (f & 3) * 4;
                pa[i] = (row < M) ? *(const float4*)(A + (long)row * K + kc)
                                  : make_float4(0.f, 0.f, 0.f, 0.f);
            }
#pragma unroll
            for (int i = 0; i < NBF; i++) {
                int f  = tid + 256 * i;
                int kr = k0 + f / (BN / 4);
                int c  = bx + (f % (BN / 4)) * 4;
                if (bvec && c + 3 < Nc) {
                    pb[i] = *(const float4*)(B + (long)kr * Nc + c);
                } else {
                    float4 v;
                    v.x = (c     < Nc) ? B[(long)kr * Nc + c    ] : 0.f;
                    v.y = (c + 1 < Nc) ? B[(long)kr * Nc + c + 1] : 0.f;
                    v.z = (c + 2 < Nc) ? B[(long)kr * Nc + c + 2] : 0.f;
                    v.w = (c + 3 < Nc) ? B[(long)kr * Nc + c + 3] : 0.f;
                    pb[i] = v;
                }
            }
        }
#pragma unroll
        for (int kk = 0; kk < BK; kk++) {
            float a[TM], b[TN];
            *(float4*)&a[0] = *(const float4*)&As[s][kk][ty * TM + 0];
            *(float4*)&a[4] = *(const float4*)&As[s][kk][ty * TM + 4];
#pragma unroll
            for (int j = 0; j < TN; j += 4)
                *(float4*)&b[j] = *(const float4*)&Bs[s][kk][tx * TN + j];
#pragma unroll
            for (int i = 0; i < TM; i++)
#pragma unroll
                for (int j = 0; j < TN; j++)
                    acc[i][j] = fmaf(a[i], b[j], acc[i][j]);
        }
        if (t + 1 < nt) {
            const int d = s ^ 1;
#pragma unroll
            for (int i = 0; i < 2; i++) {
                int f = tid + 256 * i;
                int row = f >> 2; int kq = (f & 3) * 4;
                As[d][kq + 0][row] = pa[i].x;
                As[d][kq + 1][row] = pa[i].y;
                As[d][kq + 2][row] = pa[i].z;
                As[d][kq + 3][row] = pa[i].w;
            }
#pragma unroll
            for (int i = 0; i < NBF; i++) {
                int f  = tid + 256 * i;
                int kr = f / (BN / 4);
                int c4 = (f % (BN / 4)) * 4;
                *(float4*)&Bs[d][kr][c4] = pb[i];
            }
            __syncthreads();
        }
    }

#pragma unroll
    for (int i = 0; i < TM; i++) {
        int r = by + ty * TM + i;
        if (r >= M) continue;
#pragma unroll
        for (int j = 0; j < TN; j++) {
            int c = bx + tx * TN + j;
            if (c < Nc) {
                float v = acc[i][j] + bias[c];
                C[(long)r * Nc + c] = act ? geluf(v) : v;
            }
        }
    }
}

// ---------------- LayerNorm (+optional GELU), warp per row -------------------
__global__ void ln_act(const float* __restrict__ X, const float* __restrict__ g,
                       const float* __restrict__ b, float* __restrict__ Y,
                       int M, int D, int act) {
    int warp = (blockIdx.x * blockDim.x + threadIdx.x) >> 5;
    int lane = threadIdx.x & 31;
    if (warp >= M) return;
    const float* x = X + (long)warp * D;
    int nv = D >> 5;
    float v[4];
    float s = 0.0f;
    for (int i = 0; i < nv; i++) { v[i] = x[lane + 32 * i]; s += v[i]; }
#pragma unroll
    for (int o = 16; o; o >>= 1) s += __shfl_xor_sync(0xFFFFFFFFu, s, o);
    float mean = s / (float)D;
    float q = 0.0f;
    for (int i = 0; i < nv; i++) { float d = v[i] - mean; q += d * d; }
#pragma unroll
    for (int o = 16; o; o >>= 1) q += __shfl_xor_sync(0xFFFFFFFFu, q, o);
    float inv = rsqrtf(q / (float)D + EPSF);
    float* y = Y + (long)warp * D;
    for (int i = 0; i < nv; i++) {
        int c = lane + 32 * i;
        float o2 = (v[i] - mean) * inv * g[c] + b[c];
        y[c] = act ? geluf(o2) : o2;
    }
}

// ---------------- edge feature construction ----------------------------------
__global__ void k_edge1(const float* __restrict__ pos, const int* __restrict__ ei) {
    int e = blockIdx.x * blockDim.x + threadIdx.x;
    float sd = 0.f, sx = 0.f, sy = 0.f, si = 0.f;
    if (e < Ee) {
        int r = ei[e], c = ei[Ee + e];
        float dx = pos[2 * c] - pos[2 * r];
        float dy = pos[2 * c + 1] - pos[2 * r + 1];
        float dist = sqrtf(dx * dx + dy * dy);
        dist = fmaxf(dist, 1e-6f);
        float ix = dx / dist, iy = dy / dist;
        g_ea[e * 4 + 0] = ix;
        g_ea[e * 4 + 1] = iy;
        g_ea[e * 4 + 2] = dist;
        sd = dist; sx = ix; sy = iy; si = 1.0f / dist;
    }
#pragma unroll
    for (int o = 16; o; o >>= 1) {
        sd += __shfl_xor_sync(0xFFFFFFFFu, sd, o);
        sx += __shfl_xor_sync(0xFFFFFFFFu, sx, o);
        sy += __shfl_xor_sync(0xFFFFFFFFu, sy, o);
        si += __shfl_xor_sync(0xFFFFFFFFu, si, o);
    }
    if ((threadIdx.x & 31) == 0) {
        atomicAdd(&g_red[0], sd);
        atomicAdd(&g_red[1], sx);
        atomicAdd(&g_red[2], sy);
        atomicAdd(&g_red[3], si);
    }
}

__global__ void k_edge2() {
    int i = blockIdx.x * blockDim.x + threadIdx.x;
    if (i >= ETOT) return;
    float md = fmaxf(g_red[0] / (float)Ee, 1e-6f);
    if (i < Ee) {
        float d = g_ea[i * 4 + 2];
        g_ea[i * 4 + 2] = d / md;
        g_ea[i * 4 + 3] = md / d;
    } else {
        g_ea[i * 4 + 0] = g_red[1] / (float)Ee;
        g_ea[i * 4 + 1] = g_red[2] / (float)Ee;
        g_ea[i * 4 + 2] = g_red[0] / ((float)Ee * md);
        g_ea[i * 4 + 3] = md * g_red[3] / (float)Ee;
    }
}

// ---------------- fully fused GATv2: score + softmax + aggregate -------------
// Warp per dst node. Pass 1: scores + running max (xr in regs, xl streamed).
// Pass 2: exp + head-sums + UNNORMALIZED aggregation into 16 per-lane
// accumulators (4 cols x 4 heads); xl re-read is L1/L2-hot from pass 1.
// Final: out[c] = 0.25 * sum_h acc[c][h] / u_h.  No alphas array, no agg kernel.
__global__ void k_attn(const float* __restrict__ We, const float* __restrict__ att) {
    __shared__ float sWe[4 * NHH];
    __shared__ float sAtt[NHH];
    for (int i = threadIdx.x; i < 4 * NHH; i += blockDim.x) sWe[i] = We[i];
    for (int i = threadIdx.x; i < NHH; i += blockDim.x) sAtt[i] = att[i];
    __syncthreads();

    int w = blockIdx.x * 8 + (threadIdx.x >> 5);
    if (w >= Nn) return;
    int lane = threadIdx.x & 31;
    int s0 = g_rowptr[w], s1 = g_rowptr[w + 1];

    float xr[16];
    const float* pr = g_xr + (long)w * NHH;
#pragma unroll
    for (int i = 0; i < 16; i++) xr[i] = pr[lane + 32 * i];

    float mx0 = -1e30f, mx1 = -1e30f, mx2 = -1e30f, mx3 = -1e30f;

    // pass 1: scores + running max
    for (int k = s0; k < s1; k++) {
        int src = g_esrc[k];
        float4 ea = *(const float4*)&g_ea[g_eid[k] * 4];
        const float* pl = g_xl + (long)src * NHH;
        float p0 = 0.f, p1 = 0.f, p2 = 0.f, p3 = 0.f;
#pragma unroll
        for (int i = 0; i < 16; i++) {
            int c = lane + 32 * i;
            float v = pl[c] + xr[i]
                    + ea.x * sWe[c] + ea.y * sWe[NHH + c]
                    + ea.z * sWe[2 * NHH + c] + ea.w * sWe[3 * NHH + c];
            v = v > 0.0f ? v : NEGS * v;
            float pv = v * sAtt[c];
            if (i < 4)       p0 += pv;
            else if (i < 8)  p1 += pv;
            else if (i < 12) p2 += pv;
            else             p3 += pv;
        }
#pragma unroll
        for (int o = 16; o; o >>= 1) {
            p0 += __shfl_xor_sync(0xFFFFFFFFu, p0, o);
            p1 += __shfl_xor_sync(0xFFFFFFFFu, p1, o);
            p2 += __shfl_xor_sync(0xFFFFFFFFu, p2, o);
            p3 += __shfl_xor_sync(0xFFFFFFFFu, p3, o);
        }
        mx0 = fmaxf(mx0, p0); mx1 = fmaxf(mx1, p1);
        mx2 = fmaxf(mx2, p2); mx3 = fmaxf(mx3, p3);
        if (lane == 0) *(float4*)&g_sc[k * NH] = make_float4(p0, p1, p2, p3);
    }

    // pass 2: exp + sums + unnormalized aggregation
    float u0 = 0.f, u1 = 0.f, u2 = 0.f, u3 = 0.f;
    float ac[4][4];   // [col][head]
#pragma unroll
    for (int c = 0; c < 4; c++)
#pragma unroll
        for (int h = 0; h < 4; h++) ac[c][h] = 0.0f;

    for (int k = s0; k < s1; k++) {
        float4 sc = *(const float4*)&g_sc[k * NH];
        float e0 = expf(sc.x - mx0), e1 = expf(sc.y - mx1);
        float e2 = expf(sc.z - mx2), e3 = expf(sc.w - mx3);
        u0 += e0; u1 += e1; u2 += e2; u3 += e3;
        const float* pl = g_xl + (long)g_esrc[k] * NHH;
#pragma unroll
        for (int c = 0; c < 4; c++) {
            int cc = lane + 32 * c;
            ac[c][0] += e0 * pl[cc];
            ac[c][1] += e1 * pl[HID + cc];
            ac[c][2] += e2 * pl[2 * HID + cc];
            ac[c][3] += e3 * pl[3 * HID + cc];
        }
    }
    float i0 = 1.0f / u0, i1 = 1.0f / u1, i2 = 1.0f / u2, i3 = 1.0f / u3;
    float* o = g_out + (long)w * HID;
#pragma unroll
    for (int c = 0; c < 4; c++) {
        o[lane + 32 * c] = 0.25f * (ac[c][0] * i0 + ac[c][1] * i1
                                  + ac[c][2] * i2 + ac[c][3] * i3);
    }
}

// ---------------- GraphNorm (3 passes over [N,128]) --------------------------
__global__ void k_colsum_bias(const float* __restrict__ bias, int M) {
    int col = threadIdx.x & 127;
    int half = threadIdx.x >> 7;
    int r0 = blockIdx.x * 128;
    int rend = min(r0 + 128, M);
    float s = 0.0f;
    for (int r = r0 + half; r < rend; r += 2) {
        float v = g_out[r * HID + col] + bias[col];
        g_out[r * HID + col] = v;
        s += v;
    }
    __shared__ float sh[256];
    sh[threadIdx.x] = s;
    __syncthreads();
    if (half == 0) atomicAdd(&g_col[col], sh[col] + sh[128 + col]);
}

__global__ void k_center_ss(const float* __restrict__ ga, int M) {
    int col = threadIdx.x & 127;
    int half = threadIdx.x >> 7;
    int r0 = blockIdx.x * 128;
    int rend = min(r0 + 128, M);
    float mu = g_col[col] / (float)M;
    float s = 0.0f;
    for (int r = r0 + half; r < rend; r += 2) {
        float v = g_out[r * HID + col] - ga[col] * mu;
        g_out[r * HID + col] = v;
        s += v * v;
    }
    __shared__ float sh[256];
    sh[threadIdx.x] = s;
    __syncthreads();
    if (half == 0) atomicAdd(&g_col[128 + col], sh[col] + sh[128 + col]);
}

__global__ void k_finish(const float* __restrict__ w, const float* __restrict__ b, int M) {
    int i = blockIdx.x * blockDim.x + threadIdx.x;
    if (i >= M * HID) return;
    int col = i & 127;
    float inv = rsqrtf(g_col[128 + col] / (float)M + EPSF);
    float y = g_out[i] * inv * w[col] + b[col];
    g_h[i] = geluf(y) + g_h[i];
}

// ---------------- host orchestration -----------------------------------------
extern "C" void kernel_launch(void* const* d_in, const int* in_sizes, int n_in,
                              void* d_out, int out_size) {
    const float* x        = (const float*)d_in[0];
    const int*   ei       = (const int*)  d_in[1];
    const float* pos      = (const float*)d_in[2];
    const float* in_W     = (const float*)d_in[3];
    const float* in_b     = (const float*)d_in[4];
    const float* in_ln_g  = (const float*)d_in[5];
    const float* in_ln_b  = (const float*)d_in[6];
    const float* conv_Wl  = (const float*)d_in[7];
    const float* conv_bl  = (const float*)d_in[8];
    const float* conv_Wr  = (const float*)d_in[9];
    const float* conv_br  = (const float*)d_in[10];
    const float* conv_We  = (const float*)d_in[11];
    const float* conv_att = (const float*)d_in[12];
    const float* conv_b   = (const float*)d_in[13];
    const float* gn_w     = (const float*)d_in[14];
    const float* gn_b     = (const float*)d_in[15];
    const float* gn_a     = (const float*)d_in[16];
    const float* emb_W1   = (const float*)d_in[17];
    const float* emb_b1   = (const float*)d_in[18];
    const float* emb_ln1g = (const float*)d_in[19];
    const float* emb_ln1b = (const float*)d_in[20];
    const float* emb_W2   = (const float*)d_in[21];
    const float* emb_b2   = (const float*)d_in[22];
    const float* emb_ln2g = (const float*)d_in[23];
    const float* emb_ln2b = (const float*)d_in[24];
    const float* cls_W1   = (const float*)d_in[25];
    const float* cls_b1   = (const float*)d_in[26];
    const float* cls_W2   = (const float*)d_in[27];
    const float* cls_b2   = (const float*)d_in[28];

    float *p_h, *p_t, *p_xl, *p_xr, *p_red, *p_col, *p_h1, *p_e2, *p_emb, *p_c1;
    int *p_deg;
    cudaGetSymbolAddress((void**)&p_h,    g_h);
    cudaGetSymbolAddress((void**)&p_t,    g_t);
    cudaGetSymbolAddress((void**)&p_xl,   g_xl);
    cudaGetSymbolAddress((void**)&p_xr,   g_xr);
    cudaGetSymbolAddress((void**)&p_red,  g_red);
    cudaGetSymbolAddress((void**)&p_col,  g_col);
    cudaGetSymbolAddress((void**)&p_h1,   g_h1);
    cudaGetSymbolAddress((void**)&p_e2,   g_e2);
    cudaGetSymbolAddress((void**)&p_emb,  g_emb);
    cudaGetSymbolAddress((void**)&p_c1,   g_c1);
    cudaGetSymbolAddress((void**)&p_deg,  g_deg);

    const int T = 256;
    const int GY = (Nn + 127) / 128;   // 118
    const int NWARP_GRID = (Nn * 32 + T - 1) / T;

    // ---- CSR build ----
    k_zeroi<<<(Nn + T - 1) / T, T>>>(p_deg, Nn);
    k_hist<<<(ETOT + T - 1) / T, T>>>(ei);
    k_scan<<<1, 1024>>>();
    k_scatter<<<(ETOT + T - 1) / T, T>>>(ei);

    // ---- edge features ----
    k_fill<<<1, 32>>>(p_red, 0.0f, 4);
    k_edge1<<<(Ee + T - 1) / T, T>>>(pos, ei);
    k_edge2<<<(ETOT + T - 1) / T, T>>>();

    // ---- input projection (tf32 tensor cores) ----
    tgemm<64><<<dim3(2, GY), 256>>>(x, in_W, in_b, p_t, Nn, HID, DIN, 0);
    ln_act<<<NWARP_GRID, T>>>(p_t, in_ln_g, in_ln_b, p_h, Nn, HID, 1);

    // ---- GAT layers ----
    for (int l = 0; l < NL; l++) {
        const float* Wl = conv_Wl + (long)l * HID * NHH;
        const float* bl = conv_bl + (long)l * NHH;
        const float* Wr = conv_Wr + (long)l * HID * NHH;
        const float* br = conv_br + (long)l * NHH;
        const float* We = conv_We + (long)l * 4 * NHH;
        const float* at = conv_att + (long)l * NHH;
        const float* cb = conv_b + (long)l * HID;
        const float* ga = gn_a + (long)l * HID;
        const float* gw = gn_w + (long)l * HID;
        const float* gb = gn_b + (long)l * HID;

        k_fill<<<1, 256>>>(p_col, 0.0f, 256);

        // both projection GEMMs in one grid (better wave packing)
        tgemm2<128><<<dim3(4, GY, 2), 256>>>(p_h, Wl, bl, p_xl, Wr, br, p_xr,
                                             Nn, NHH, HID);

        k_attn<<<(Nn + 7) / 8, 256>>>(We, at);

        int nb = (Nn + 127) / 128;
        k_colsum_bias<<<nb, 256>>>(cb, Nn);
        k_center_ss<<<nb, 256>>>(ga, Nn);
        k_finish<<<(Nn * HID + T - 1) / T, T>>>(gw, gb, Nn);
    }

    // ---- embedding head ----
    tgemm<64><<<dim3(2, GY), 256>>>(p_h, emb_W1, emb_b1, p_t, Nn, HID, HID, 0);
    ln_act<<<NWARP_GRID, T>>>(p_t, emb_ln1g, emb_ln1b, p_h1, Nn, HID, 1);
    tgemm<64><<<dim3(1, GY), 256>>>(p_h1, emb_W2, emb_b2, p_e2, Nn, EMBD, HID, 0);
    ln_act<<<NWARP_GRID, T>>>(p_e2, emb_ln2g, emb_ln2b, p_emb, Nn, EMBD, 0);
    tgemm<64><<<dim3(1, GY), 256>>>(p_emb, cls_W1, cls_b1, p_c1, Nn, EMBD, EMBD, 1);
    sgemm_db<64, 4><<<dim3(1, GY), 256>>>(p_c1, cls_W2, cls_b2, (float*)d_out, Nn, NCLS, EMBD, 0);
}

// round 10
// speedup vs baseline: 1.0888x; 1.0225x over previous
#include <cuda_runtime.h>
#include <math.h>

#define Nn   15000
#define Ee   240000
#define ETOT (Ee + Nn)
#define DIN  2000
#define HID  128
#define EMBD 64
#define NCLS 33
#define NL   3
#define NH   4
#define NHH  (NH * HID)   // 512
#define NEGS 0.2f
#define EPSF 1e-5f

// ---------------- scratch (static device memory; no allocs allowed) ----------
__device__ float g_h   [Nn * HID];
__device__ float g_t   [Nn * HID];
__device__ float g_xl  [Nn * NHH];
__device__ float g_xr  [Nn * NHH];
__device__ float g_ea  [ETOT * 4];
__device__ float g_sc  [ETOT * NH];   // CSR-ordered raw scores
__device__ float g_out [Nn * HID];
__device__ float g_red [4];
__device__ float g_col [2 * HID];     // [0:128) sum(o), [128:256) sum(o^2)
__device__ float g_h1  [Nn * HID];
__device__ float g_e2  [Nn * EMBD];
__device__ float g_emb [Nn * EMBD];
__device__ float g_c1  [Nn * EMBD];
__device__ int g_deg   [Nn];
__device__ int g_rowptr[Nn + 1];
__device__ int g_cur   [Nn];
__device__ int g_eid   [ETOT];
__device__ int g_esrc  [ETOT];

// ---------------- helpers ----------------------------------------------------
__device__ __forceinline__ float geluf(float x) {
    return 0.5f * x * (1.0f + erff(x * 0.70710678118654752f));
}

__device__ __forceinline__ unsigned f2tf(float f) {
    unsigned r;
    asm("cvt.rna.tf32.f32 %0, %1;" : "=r"(r) : "f"(f));
    return r;
}

__global__ void k_fill(float* p, float v, int n) {
    int i = blockIdx.x * blockDim.x + threadIdx.x;
    if (i < n) p[i] = v;
}

__global__ void k_zeroi(int* p, int n) {
    int i = blockIdx.x * blockDim.x + threadIdx.x;
    if (i < n) p[i] = 0;
}

// ---------------- CSR build --------------------------------------------------
__global__ void k_hist(const int* __restrict__ ei) {
    int e = blockIdx.x * blockDim.x + threadIdx.x;
    if (e >= ETOT) return;
    int dst = (e < Ee) ? ei[Ee + e] : e - Ee;
    atomicAdd(&g_deg[dst], 1);
}

__global__ void k_scan() {
    __shared__ int sh[1024];
    const int C = 15;
    int t = threadIdx.x;
    int base = t * C;
    int local[C];
    int s = 0;
    for (int i = 0; i < C; i++) {
        int idx = base + i;
        int v = (idx < Nn) ? g_deg[idx] : 0;
        local[i] = s;
        s += v;
    }
    sh[t] = s;
    __syncthreads();
    for (int o = 1; o < 1024; o <<= 1) {
        int v = (t >= o) ? sh[t - o] : 0;
        __syncthreads();
        sh[t] += v;
        __syncthreads();
    }
    int off = (t > 0) ? sh[t - 1] : 0;
    for (int i = 0; i < C; i++) {
        int idx = base + i;
        if (idx < Nn) {
            g_rowptr[idx] = off + local[i];
            g_cur[idx]    = off + local[i];
        }
    }
    if (t == 1023) g_rowptr[Nn] = sh[1023];
}

__global__ void k_scatter(const int* __restrict__ ei) {
    int e = blockIdx.x * blockDim.x + threadIdx.x;
    if (e >= ETOT) return;
    int src, dst;
    if (e < Ee) { src = ei[e]; dst = ei[Ee + e]; } else { src = dst = e - Ee; }
    int p = atomicAdd(&g_cur[dst], 1);
    g_eid[p]  = e;
    g_esrc[p] = src;
}

// ---------------- tf32 tensor-core GEMM core ---------------------------------
template<int BN>
__device__ __forceinline__ void tgemm_body(
    const float* __restrict__ A, const float* __restrict__ B,
    const float* __restrict__ bias, float* __restrict__ C,
    int M, int Nc, int K, int act, int bxBlk, int byBlk) {
    constexpr int BM = 128, BK = 16;
    constexpr int WN = BN / 2;
    constexpr int NT = WN / 8;
    constexpr int NBF = (BK * BN / 4) / 256;
    __shared__ unsigned As[2][BK][BM + 4];
    __shared__ unsigned Bs[2][BK][BN + 4];

    const int tid  = threadIdx.x;
    const int lane = tid & 31;
    const int wid  = tid >> 5;
    const int m0   = (wid & 3) * 32;
    const int n0   = (wid >> 2) * WN;
    const int gp   = lane >> 2;
    const int tk   = lane & 3;
    const int bx   = bxBlk * BN;
    const int by   = byBlk * BM;

    float4 pa[2], pb[NBF];
    float acc[2][NT][4];
#pragma unroll
    for (int i = 0; i < 2; i++)
#pragma unroll
        for (int j = 0; j < NT; j++)
#pragma unroll
            for (int q = 0; q < 4; q++) acc[i][j][q] = 0.0f;

    const int nt = K / BK;

    auto loadA = [&](int k0) {
#pragma unroll
        for (int i = 0; i < 2; i++) {
            int f = tid + 256 * i;
            int row = by + (f >> 2);
            int kc  = k0 + (f & 3) * 4;
            pa[i] = (row < M) ? *(const float4*)(A + (long)row * K + kc)
                              : make_float4(0.f, 0.f, 0.f, 0.f);
        }
    };
    auto loadB = [&](int k0) {
#pragma unroll
        for (int i = 0; i < NBF; i++) {
            int f  = tid + 256 * i;
            int kr = k0 + f / (BN / 4);
            int c  = bx + (f % (BN / 4)) * 4;
            if (c + 3 < Nc) {
                pb[i] = *(const float4*)(B + (long)kr * Nc + c);
            } else {
                float4 v;
                v.x = (c     < Nc) ? B[(long)kr * Nc + c    ] : 0.f;
                v.y = (c + 1 < Nc) ? B[(long)kr * Nc + c + 1] : 0.f;
                v.z = (c + 2 < Nc) ? B[(long)kr * Nc + c + 2] : 0.f;
                v.w = (c + 3 < Nc) ? B[(long)kr * Nc + c + 3] : 0.f;
                pb[i] = v;
            }
        }
    };
    auto store = [&](int d) {
#pragma unroll
        for (int i = 0; i < 2; i++) {
            int f = tid + 256 * i;
            int row = f >> 2; int kq = (f & 3) * 4;
            As[d][kq + 0][row] = f2tf(pa[i].x);
            As[d][kq + 1][row] = f2tf(pa[i].y);
            As[d][kq + 2][row] = f2tf(pa[i].z);
            As[d][kq + 3][row] = f2tf(pa[i].w);
        }
#pragma unroll
        for (int i = 0; i < NBF; i++) {
            int f  = tid + 256 * i;
            int kr = f / (BN / 4);
            int c4 = (f % (BN / 4)) * 4;
            Bs[d][kr][c4 + 0] = f2tf(pb[i].x);
            Bs[d][kr][c4 + 1] = f2tf(pb[i].y);
            Bs[d][kr][c4 + 2] = f2tf(pb[i].z);
            Bs[d][kr][c4 + 3] = f2tf(pb[i].w);
        }
    };

    loadA(0); loadB(0); store(0);
    __syncthreads();

    for (int t = 0; t < nt; t++) {
        const int s = t & 1;
        if (t + 1 < nt) { loadA((t + 1) * BK); loadB((t + 1) * BK); }
#pragma unroll
        for (int k8 = 0; k8 < BK; k8 += 8) {
            unsigned a[2][4], b[NT][2];
#pragma unroll
            for (int mt = 0; mt < 2; mt++) {
                int mr = m0 + mt * 16;
                a[mt][0] = As[s][k8 + tk    ][mr + gp    ];
                a[mt][1] = As[s][k8 + tk    ][mr + gp + 8];
                a[mt][2] = As[s][k8 + tk + 4][mr + gp    ];
                a[mt][3] = As[s][k8 + tk + 4][mr + gp + 8];
            }
#pragma unroll
            for (int j = 0; j < NT; j++) {
                int nc = n0 + j * 8 + gp;
                b[j][0] = Bs[s][k8 + tk    ][nc];
                b[j][1] = Bs[s][k8 + tk + 4][nc];
            }
#pragma unroll
            for (int mt = 0; mt < 2; mt++)
#pragma unroll
                for (int j = 0; j < NT; j++) {
                    asm volatile(
                        "mma.sync.aligned.m16n8k8.row.col.f32.tf32.tf32.f32 "
                        "{%0,%1,%2,%3}, {%4,%5,%6,%7}, {%8,%9}, {%0,%1,%2,%3};\n"
                        : "+f"(acc[mt][j][0]), "+f"(acc[mt][j][1]),
                          "+f"(acc[mt][j][2]), "+f"(acc[mt][j][3])
                        : "r"(a[mt][0]), "r"(a[mt][1]), "r"(a[mt][2]), "r"(a[mt][3]),
                          "r"(b[j][0]), "r"(b[j][1]));
                }
        }
        if (t + 1 < nt) {
            store(s ^ 1);
            __syncthreads();
        }
    }

#pragma unroll
    for (int mt = 0; mt < 2; mt++) {
        int r0 = by + m0 + mt * 16 + gp;
        int r1 = r0 + 8;
#pragma unroll
        for (int j = 0; j < NT; j++) {
            int c0 = bx + n0 + j * 8 + tk * 2;
            if (r0 < M) {
                if (c0 < Nc) {
                    float v = acc[mt][j][0] + bias[c0];
                    C[(long)r0 * Nc + c0] = act ? geluf(v) : v;
                }
                if (c0 + 1 < Nc) {
                    float v = acc[mt][j][1] + bias[c0 + 1];
                    C[(long)r0 * Nc + c0 + 1] = act ? geluf(v) : v;
                }
            }
            if (r1 < M) {
                if (c0 < Nc) {
                    float v = acc[mt][j][2] + bias[c0];
                    C[(long)r1 * Nc + c0] = act ? geluf(v) : v;
                }
                if (c0 + 1 < Nc) {
                    float v = acc[mt][j][3] + bias[c0 + 1];
                    C[(long)r1 * Nc + c0 + 1] = act ? geluf(v) : v;
                }
            }
        }
    }
}

template<int BN>
__global__ void __launch_bounds__(256)
tgemm(const float* __restrict__ A, const float* __restrict__ B,
      const float* __restrict__ bias, float* __restrict__ C,
      int M, int Nc, int K, int act) {
    tgemm_body<BN>(A, B, bias, C, M, Nc, K, act, blockIdx.x, blockIdx.y);
}

template<int BN>
__global__ void __launch_bounds__(256)
tgemm2(const float* __restrict__ A,
       const float* __restrict__ B1, const float* __restrict__ bias1, float* __restrict__ C1,
       const float* __restrict__ B2, const float* __restrict__ bias2, float* __restrict__ C2,
       int M, int Nc, int K) {
    if (blockIdx.z == 0)
        tgemm_body<BN>(A, B1, bias1, C1, M, Nc, K, 0, blockIdx.x, blockIdx.y);
    else
        tgemm_body<BN>(A, B2, bias2, C2, M, Nc, K, 0, blockIdx.x, blockIdx.y);
}

// ---------------- small SIMT GEMM (for Nc=33 classifier) ---------------------
template<int BN, int TN>
__global__ void __launch_bounds__(256)
sgemm_db(const float* __restrict__ A, const float* __restrict__ B,
         const float* __restrict__ bias, float* __restrict__ C,
         int M, int Nc, int K, int act) {
    constexpr int BM = 128, BK = 16, TM = 8;
    constexpr int NBF = (BK * BN / 4) / 256;
    __shared__ float As[2][BK][BM + 4];
    __shared__ float Bs[2][BK][BN + 4];
    const int tid = threadIdx.x;
    const int tx  = tid % (BN / TN);
    const int ty  = tid / (BN / TN);
    const int bx  = blockIdx.x * BN;
    const int by  = blockIdx.y * BM;
    const bool bvec = ((Nc & 3) == 0);

    float4 pa[2], pb[NBF];
    float acc[TM][TN];
#pragma unroll
    for (int i = 0; i < TM; i++)
#pragma unroll
        for (int j = 0; j < TN; j++) acc[i][j] = 0.0f;

    const int nt = K / BK;

#pragma unroll
    for (int i = 0; i < 2; i++) {
        int f = tid + 256 * i;
        int row = by + (f >> 2);
        int kc  = (f & 3) * 4;
        pa[i] = (row < M) ? *(const float4*)(A + (long)row * K + kc)
                          : make_float4(0.f, 0.f, 0.f, 0.f);
    }
#pragma unroll
    for (int i = 0; i < NBF; i++) {
        int f  = tid + 256 * i;
        int kr = f / (BN / 4);
        int c  = bx + (f % (BN / 4)) * 4;
        if (bvec && c + 3 < Nc) {
            pb[i] = *(const float4*)(B + (long)kr * Nc + c);
        } else {
            float4 v;
            v.x = (c     < Nc) ? B[(long)kr * Nc + c    ] : 0.f;
            v.y = (c + 1 < Nc) ? B[(long)kr * Nc + c + 1] : 0.f;
            v.z = (c + 2 < Nc) ? B[(long)kr * Nc + c + 2] : 0.f;
            v.w = (c + 3 < Nc) ? B[(long)kr * Nc + c + 3] : 0.f;
            pb[i] = v;
        }
    }
#pragma unroll
    for (int i = 0; i < 2; i++) {
        int f = tid + 256 * i;
        int row = f >> 2; int kq = (f & 3) * 4;
        As[0][kq + 0][row] = pa[i].x;
        As[0][kq + 1][row] = pa[i].y;
        As[0][kq + 2][row] = pa[i].z;
        As[0][kq + 3][row] = pa[i].w;
    }
#pragma unroll
    for (int i = 0; i < NBF; i++) {
        int f  = tid + 256 * i;
        int kr = f / (BN / 4);
        int c4 = (f % (BN / 4)) * 4;
        *(float4*)&Bs[0][kr][c4] = pb[i];
    }
    __syncthreads();

    for (int t = 0; t < nt; t++) {
        const int s = t & 1;
        if (t + 1 < nt) {
            const int k0 = (t + 1) * BK;
#pragma unroll
            for (int i = 0; i < 2; i++) {
                int f = tid + 256 * i;
                int row = by + (f >> 2);
                int kc  = k0 + (f & 3) * 4;
                pa[i] = (row < M) ? *(const float4*)(A + (long)row * K + kc)
                                  : make_float4(0.f, 0.f, 0.f, 0.f);
            }
#pragma unroll
            for (int i = 0; i < NBF; i++) {
                int f  = tid + 256 * i;
                int kr = k0 + f / (BN / 4);
                int c  = bx + (f % (BN / 4)) * 4;
                if (bvec && c + 3 < Nc) {
                    pb[i] = *(const float4*)(B + (long)kr * Nc + c);
                } else {
                    float4 v;
                    v.x = (c     < Nc) ? B[(long)kr * Nc + c    ] : 0.f;
                    v.y = (c + 1 < Nc) ? B[(long)kr * Nc + c + 1] : 0.f;
                    v.z = (c + 2 < Nc) ? B[(long)kr * Nc + c + 2] : 0.f;
                    v.w = (c + 3 < Nc) ? B[(long)kr * Nc + c + 3] : 0.f;
                    pb[i] = v;
                }
            }
        }
#pragma unroll
        for (int kk = 0; kk < BK; kk++) {
            float a[TM], b[TN];
            *(float4*)&a[0] = *(const float4*)&As[s][kk][ty * TM + 0];
            *(float4*)&a[4] = *(const float4*)&As[s][kk][ty * TM + 4];
#pragma unroll
            for (int j = 0; j < TN; j += 4)
                *(float4*)&b[j] = *(const float4*)&Bs[s][kk][tx * TN + j];
#pragma unroll
            for (int i = 0; i < TM; i++)
#pragma unroll
                for (int j = 0; j < TN; j++)
                    acc[i][j] = fmaf(a[i], b[j], acc[i][j]);
        }
        if (t + 1 < nt) {
            const int d = s ^ 1;
#pragma unroll
            for (int i = 0; i < 2; i++) {
                int f = tid + 256 * i;
                int row = f >> 2; int kq = (f & 3) * 4;
                As[d][kq + 0][row] = pa[i].x;
                As[d][kq + 1][row] = pa[i].y;
                As[d][kq + 2][row] = pa[i].z;
                As[d][kq + 3][row] = pa[i].w;
            }
#pragma unroll
            for (int i = 0; i < NBF; i++) {
                int f  = tid + 256 * i;
                int kr = f / (BN / 4);
                int c4 = (f % (BN / 4)) * 4;
                *(float4*)&Bs[d][kr][c4] = pb[i];
            }
            __syncthreads();
        }
    }

#pragma unroll
    for (int i = 0; i < TM; i++) {
        int r = by + ty * TM + i;
        if (r >= M) continue;
#pragma unroll
        for (int j = 0; j < TN; j++) {
            int c = bx + tx * TN + j;
            if (c < Nc) {
                float v = acc[i][j] + bias[c];
                C[(long)r * Nc + c] = act ? geluf(v) : v;
            }
        }
    }
}

// ---------------- LayerNorm (+optional GELU), warp per row -------------------
__global__ void ln_act(const float* __restrict__ X, const float* __restrict__ g,
                       const float* __restrict__ b, float* __restrict__ Y,
                       int M, int D, int act) {
    int warp = (blockIdx.x * blockDim.x + threadIdx.x) >> 5;
    int lane = threadIdx.x & 31;
    if (warp >= M) return;
    const float* x = X + (long)warp * D;
    int nv = D >> 5;
    float v[4];
    float s = 0.0f;
    for (int i = 0; i < nv; i++) { v[i] = x[lane + 32 * i]; s += v[i]; }
#pragma unroll
    for (int o = 16; o; o >>= 1) s += __shfl_xor_sync(0xFFFFFFFFu, s, o);
    float mean = s / (float)D;
    float q = 0.0f;
    for (int i = 0; i < nv; i++) { float d = v[i] - mean; q += d * d; }
#pragma unroll
    for (int o = 16; o; o >>= 1) q += __shfl_xor_sync(0xFFFFFFFFu, q, o);
    float inv = rsqrtf(q / (float)D + EPSF);
    float* y = Y + (long)warp * D;
    for (int i = 0; i < nv; i++) {
        int c = lane + 32 * i;
        float o2 = (v[i] - mean) * inv * g[c] + b[c];
        y[c] = act ? geluf(o2) : o2;
    }
}

// ---------------- edge feature construction ----------------------------------
__global__ void k_edge1(const float* __restrict__ pos, const int* __restrict__ ei) {
    int e = blockIdx.x * blockDim.x + threadIdx.x;
    float sd = 0.f, sx = 0.f, sy = 0.f, si = 0.f;
    if (e < Ee) {
        int r = ei[e], c = ei[Ee + e];
        float dx = pos[2 * c] - pos[2 * r];
        float dy = pos[2 * c + 1] - pos[2 * r + 1];
        float dist = sqrtf(dx * dx + dy * dy);
        dist = fmaxf(dist, 1e-6f);
        float ix = dx / dist, iy = dy / dist;
        g_ea[e * 4 + 0] = ix;
        g_ea[e * 4 + 1] = iy;
        g_ea[e * 4 + 2] = dist;
        sd = dist; sx = ix; sy = iy; si = 1.0f / dist;
    }
#pragma unroll
    for (int o = 16; o; o >>= 1) {
        sd += __shfl_xor_sync(0xFFFFFFFFu, sd, o);
        sx += __shfl_xor_sync(0xFFFFFFFFu, sx, o);
        sy += __shfl_xor_sync(0xFFFFFFFFu, sy, o);
        si += __shfl_xor_sync(0xFFFFFFFFu, si, o);
    }
    if ((threadIdx.x & 31) == 0) {
        atomicAdd(&g_red[0], sd);
        atomicAdd(&g_red[1], sx);
        atomicAdd(&g_red[2], sy);
        atomicAdd(&g_red[3], si);
    }
}

__global__ void k_edge2() {
    int i = blockIdx.x * blockDim.x + threadIdx.x;
    if (i >= ETOT) return;
    float md = fmaxf(g_red[0] / (float)Ee, 1e-6f);
    if (i < Ee) {
        float d = g_ea[i * 4 + 2];
        g_ea[i * 4 + 2] = d / md;
        g_ea[i * 4 + 3] = md / d;
    } else {
        g_ea[i * 4 + 0] = g_red[1] / (float)Ee;
        g_ea[i * 4 + 1] = g_red[2] / (float)Ee;
        g_ea[i * 4 + 2] = g_red[0] / ((float)Ee * md);
        g_ea[i * 4 + 3] = md * g_red[3] / (float)Ee;
    }
}

// ---------------- fully fused GATv2 + GraphNorm stats ------------------------
// Warp per dst node (grid exactly Nn/8 blocks). Pass 1: scores + running max.
// Pass 2: exp + head-sums + unnormalized aggregation. Epilogue: add conv bias,
// write g_out once, and accumulate per-block column sums of o and o^2 into
// g_col via smem staging (for the closed-form GraphNorm in k_finish).
__global__ void k_attn(const float* __restrict__ We, const float* __restrict__ att,
                       const float* __restrict__ cbias) {
    __shared__ float sWe[4 * NHH];
    __shared__ float sAtt[NHH];
    __shared__ float sSum[HID];
    __shared__ float sSq[HID];
    for (int i = threadIdx.x; i < 4 * NHH; i += blockDim.x) sWe[i] = We[i];
    for (int i = threadIdx.x; i < NHH; i += blockDim.x) sAtt[i] = att[i];
    if (threadIdx.x < HID) { sSum[threadIdx.x] = 0.f; sSq[threadIdx.x] = 0.f; }
    __syncthreads();

    int w = blockIdx.x * 8 + (threadIdx.x >> 5);    // Nn % 8 == 0: always valid
    int lane = threadIdx.x & 31;
    int s0 = g_rowptr[w], s1 = g_rowptr[w + 1];

    float xr[16];
    const float* pr = g_xr + (long)w * NHH;
#pragma unroll
    for (int i = 0; i < 16; i++) xr[i] = pr[lane + 32 * i];

    float mx0 = -1e30f, mx1 = -1e30f, mx2 = -1e30f, mx3 = -1e30f;

    // pass 1: scores + running max
    for (int k = s0; k < s1; k++) {
        int src = g_esrc[k];
        float4 ea = *(const float4*)&g_ea[g_eid[k] * 4];
        const float* pl = g_xl + (long)src * NHH;
        float p0 = 0.f, p1 = 0.f, p2 = 0.f, p3 = 0.f;
#pragma unroll
        for (int i = 0; i < 16; i++) {
            int c = lane + 32 * i;
            float v = pl[c] + xr[i]
                    + ea.x * sWe[c] + ea.y * sWe[NHH + c]
                    + ea.z * sWe[2 * NHH + c] + ea.w * sWe[3 * NHH + c];
            v = v > 0.0f ? v : NEGS * v;
            float pv = v * sAtt[c];
            if (i < 4)       p0 += pv;
            else if (i < 8)  p1 += pv;
            else if (i < 12) p2 += pv;
            else             p3 += pv;
        }
#pragma unroll
        for (int o = 16; o; o >>= 1) {
            p0 += __shfl_xor_sync(0xFFFFFFFFu, p0, o);
            p1 += __shfl_xor_sync(0xFFFFFFFFu, p1, o);
            p2 += __shfl_xor_sync(0xFFFFFFFFu, p2, o);
            p3 += __shfl_xor_sync(0xFFFFFFFFu, p3, o);
        }
        mx0 = fmaxf(mx0, p0); mx1 = fmaxf(mx1, p1);
        mx2 = fmaxf(mx2, p2); mx3 = fmaxf(mx3, p3);
        if (lane == 0) *(float4*)&g_sc[k * NH] = make_float4(p0, p1, p2, p3);
    }

    // pass 2: exp + sums + unnormalized aggregation
    float u0 = 0.f, u1 = 0.f, u2 = 0.f, u3 = 0.f;
    float ac[4][4];
#pragma unroll
    for (int c = 0; c < 4; c++)
#pragma unroll
        for (int h = 0; h < 4; h++) ac[c][h] = 0.0f;

    for (int k = s0; k < s1; k++) {
        float4 sc = *(const float4*)&g_sc[k * NH];
        float e0 = expf(sc.x - mx0), e1 = expf(sc.y - mx1);
        float e2 = expf(sc.z - mx2), e3 = expf(sc.w - mx3);
        u0 += e0; u1 += e1; u2 += e2; u3 += e3;
        const float* pl = g_xl + (long)g_esrc[k] * NHH;
#pragma unroll
        for (int c = 0; c < 4; c++) {
            int cc = lane + 32 * c;
            ac[c][0] += e0 * pl[cc];
            ac[c][1] += e1 * pl[HID + cc];
            ac[c][2] += e2 * pl[2 * HID + cc];
            ac[c][3] += e3 * pl[3 * HID + cc];
        }
    }
    float i0 = 1.0f / u0, i1 = 1.0f / u1, i2 = 1.0f / u2, i3 = 1.0f / u3;
    float* o = g_out + (long)w * HID;
#pragma unroll
    for (int c = 0; c < 4; c++) {
        int col = lane + 32 * c;
        float v = 0.25f * (ac[c][0] * i0 + ac[c][1] * i1
                         + ac[c][2] * i2 + ac[c][3] * i3) + cbias[col];
        o[col] = v;
        atomicAdd(&sSum[col], v);
        atomicAdd(&sSq[col], v * v);
    }
    __syncthreads();
    if (threadIdx.x < HID) {
        atomicAdd(&g_col[threadIdx.x], sSum[threadIdx.x]);
        atomicAdd(&g_col[HID + threadIdx.x], sSq[threadIdx.x]);
    }
}

// ---------------- GraphNorm finish (single pass, closed-form variance) -------
// mu = E[o], ms = E[o^2]; var of (o - a*mu) = ms - 2a*mu^2 + a^2*mu^2.
__global__ void k_finish(const float* __restrict__ ga, const float* __restrict__ w,
                         const float* __restrict__ b, int M) {
    int i = blockIdx.x * blockDim.x + threadIdx.x;
    if (i >= M * HID) return;
    int col = i & 127;
    float mu = g_col[col] / (float)M;
    float ms = g_col[HID + col] / (float)M;
    float a  = ga[col];
    float var = ms - 2.0f * a * mu * mu + a * a * mu * mu;
    float inv = rsqrtf(var + EPSF);
    float y = (g_out[i] - a * mu) * inv * w[col] + b[col];
    g_h[i] = geluf(y) + g_h[i];
}

// ---------------- host orchestration -----------------------------------------
extern "C" void kernel_launch(void* const* d_in, const int* in_sizes, int n_in,
                              void* d_out, int out_size) {
    const float* x        = (const float*)d_in[0];
    const int*   ei       = (const int*)  d_in[1];
    const float* pos      = (const float*)d_in[2];
    const float* in_W     = (const float*)d_in[3];
    const float* in_b     = (const float*)d_in[4];
    const float* in_ln_g  = (const float*)d_in[5];
    const float* in_ln_b  = (const float*)d_in[6];
    const float* conv_Wl  = (const float*)d_in[7];
    const float* conv_bl  = (const float*)d_in[8];
    const float* conv_Wr  = (const float*)d_in[9];
    const float* conv_br  = (const float*)d_in[10];
    const float* conv_We  = (const float*)d_in[11];
    const float* conv_att = (const float*)d_in[12];
    const float* conv_b   = (const float*)d_in[13];
    const float* gn_w     = (const float*)d_in[14];
    const float* gn_b     = (const float*)d_in[15];
    const float* gn_a     = (const float*)d_in[16];
    const float* emb_W1   = (const float*)d_in[17];
    const float* emb_b1   = (const float*)d_in[18];
    const float* emb_ln1g = (const float*)d_in[19];
    const float* emb_ln1b = (const float*)d_in[20];
    const float* emb_W2   = (const float*)d_in[21];
    const float* emb_b2   = (const float*)d_in[22];
    const float* emb_ln2g = (const float*)d_in[23];
    const float* emb_ln2b = (const float*)d_in[24];
    const float* cls_W1   = (const float*)d_in[25];
    const float* cls_b1   = (const float*)d_in[26];
    const float* cls_W2   = (const float*)d_in[27];
    const float* cls_b2   = (const float*)d_in[28];

    float *p_h, *p_t, *p_xl, *p_xr, *p_red, *p_col, *p_h1, *p_e2, *p_emb, *p_c1;
    int *p_deg;
    cudaGetSymbolAddress((void**)&p_h,    g_h);
    cudaGetSymbolAddress((void**)&p_t,    g_t);
    cudaGetSymbolAddress((void**)&p_xl,   g_xl);
    cudaGetSymbolAddress((void**)&p_xr,   g_xr);
    cudaGetSymbolAddress((void**)&p_red,  g_red);
    cudaGetSymbolAddress((void**)&p_col,  g_col);
    cudaGetSymbolAddress((void**)&p_h1,   g_h1);
    cudaGetSymbolAddress((void**)&p_e2,   g_e2);
    cudaGetSymbolAddress((void**)&p_emb,  g_emb);
    cudaGetSymbolAddress((void**)&p_c1,   g_c1);
    cudaGetSymbolAddress((void**)&p_deg,  g_deg);

    const int T = 256;
    const int GY = (Nn + 127) / 128;   // 118
    const int NWARP_GRID = (Nn * 32 + T - 1) / T;

    // ---- CSR build ----
    k_zeroi<<<(Nn + T - 1) / T, T>>>(p_deg, Nn);
    k_hist<<<(ETOT + T - 1) / T, T>>>(ei);
    k_scan<<<1, 1024>>>();
    k_scatter<<<(ETOT + T - 1) / T, T>>>(ei);

    // ---- edge features ----
    k_fill<<<1, 32>>>(p_red, 0.0f, 4);
    k_edge1<<<(Ee + T - 1) / T, T>>>(pos, ei);
    k_edge2<<<(ETOT + T - 1) / T, T>>>();

    // ---- input projection (tf32 tensor cores) ----
    tgemm<64><<<dim3(2, GY), 256>>>(x, in_W, in_b, p_t, Nn, HID, DIN, 0);
    ln_act<<<NWARP_GRID, T>>>(p_t, in_ln_g, in_ln_b, p_h, Nn, HID, 1);

    // ---- GAT layers ----
    for (int l = 0; l < NL; l++) {
        const float* Wl = conv_Wl + (long)l * HID * NHH;
        const float* bl = conv_bl + (long)l * NHH;
        const float* Wr = conv_Wr + (long)l * HID * NHH;
        const float* br = conv_br + (long)l * NHH;
        const float* We = conv_We + (long)l * 4 * NHH;
        const float* at = conv_att + (long)l * NHH;
        const float* cb = conv_b + (long)l * HID;
        const float* ga = gn_a + (long)l * HID;
        const float* gw = gn_w + (long)l * HID;
        const float* gb = gn_b + (long)l * HID;

        k_fill<<<1, 256>>>(p_col, 0.0f, 256);

        tgemm2<128><<<dim3(4, GY, 2), 256>>>(p_h, Wl, bl, p_xl, Wr, br, p_xr,
                                             Nn, NHH, HID);

        k_attn<<<Nn / 8, 256>>>(We, at, cb);

        k_finish<<<(Nn * HID + T - 1) / T, T>>>(ga, gw, gb, Nn);
    }

    // ---- embedding head ----
    tgemm<64><<<dim3(2, GY), 256>>>(p_h, emb_W1, emb_b1, p_t, Nn, HID, HID, 0);
    ln_act<<<NWARP_GRID, T>>>(p_t, emb_ln1g, emb_ln1b, p_h1, Nn, HID, 1);
    tgemm<64><<<dim3(1, GY), 256>>>(p_h1, emb_W2, emb_b2, p_e2, Nn, EMBD, HID, 0);
    ln_act<<<NWARP_GRID, T>>>(p_e2, emb_ln2g, emb_ln2b, p_emb, Nn, EMBD, 0);
    tgemm<64><<<dim3(1, GY), 256>>>(p_emb, cls_W1, cls_b1, p_c1, Nn, EMBD, EMBD, 1);
    sgemm_db<64, 4><<<dim3(1, GY), 256>>>(p_c1, cls_W2, cls_b2, (float*)d_out, Nn, NCLS, EMBD, 0);
}